// round 12
// baseline (speedup 1.0000x reference)
#include <cuda_runtime.h>
#include <stdint.h>

#define HDIM 256
#define TS   256
#define BTOT 4096
#define BC   14
#define NP   7
#define NBLK ((BTOT + BC - 1) / BC)   // 293

// Repacked W: g_Wp[h4*256 + g] = float4{ W[g][4h4 .. 4h4+3] }  (coalesced across g)
__device__ float4 g_Wp[64 * 256];

__global__ void pack_w_kernel(const float* __restrict__ W) {
    int idx = blockIdx.x * blockDim.x + threadIdx.x;   // 0..16383
    int h4 = idx >> 8, gg = idx & 255;
    const float4* Wv = (const float4*)W;
    g_Wp[idx] = Wv[gg * 64 + h4];
}

// Threefry-2x32, 20 rounds — matches jax._src.prng.threefry2x32 exactly.
__device__ __forceinline__ uint2 tf2x32(uint32_t k0, uint32_t k1, uint32_t c0, uint32_t c1) {
    uint32_t ks2 = k0 ^ k1 ^ 0x1BD11BDAu;
    uint32_t x0 = c0 + k0, x1 = c1 + k1;
#define TFR(r) { x0 += x1; x1 = __funnelshift_l(x1, x1, r); x1 ^= x0; }
    TFR(13) TFR(15) TFR(26) TFR(6)
    x0 += k1;  x1 += ks2 + 1u;
    TFR(17) TFR(29) TFR(16) TFR(24)
    x0 += ks2; x1 += k0 + 2u;
    TFR(13) TFR(15) TFR(26) TFR(6)
    x0 += k0;  x1 += k1 + 3u;
    TFR(17) TFR(29) TFR(16) TFR(24)
    x0 += k1;  x1 += ks2 + 4u;
    TFR(13) TFR(15) TFR(26) TFR(6)
    x0 += ks2; x1 += k0 + 5u;
#undef TFR
    return make_uint2(x0, x1);
}

// jax.random.normal, threefry-partitionable path (default since JAX 0.4.36):
// bits[j] = x0 ^ x1 of threefry(key, (hi=0, lo=j)); uniform in [nextafter(-1,0), 1); sqrt(2)*erfinv.
__device__ __forceinline__ float jax_normal(uint2 key, uint32_t j) {
    uint2 r = tf2x32(key.x, key.y, 0u, j);
    uint32_t bits = r.x ^ r.y;
    float f = __uint_as_float((bits >> 9) | 0x3F800000u) - 1.0f;
    const float LO = -0.99999994f;               // nextafter(-1, 0)
    float u = fmaxf(LO, fmaf(f, 2.0f, LO));      // (hi-lo) rounds to 2.0f in fp32
    return 1.41421356f * erfinvf(u);
}

#define FMA2(d, a, b)     asm("fma.rn.f32x2 %0, %1, %2, %0;" : "+l"(d) : "l"(a), "l"(b))
#define PACK2(out, lo, hi) asm("mov.b64 %0, {%1, %2};" : "=l"(out) : "r"(lo), "r"(hi))
#define UNPACK2(lo, hi, in) asm("mov.b64 {%0, %1}, %2;" : "=r"(lo), "=r"(hi) : "l"(in))

__global__ __launch_bounds__(256, 2)
void drnet_kernel(const float* __restrict__ img, const float* __restrict__ W_ih,
                  const float* __restrict__ b_ih, const float* __restrict__ b_hh,
                  float* __restrict__ out) {
    // latent stored pair-interleaved for packed f32x2 math: Lp[p][h][j] = latent[2p+j][h]
    __shared__ __align__(16) float Lp[NP][HDIM][2];
    __shared__ float Xs[BC][TS];
    __shared__ uint2 Ks[TS];

    const int g = threadIdx.x;          // output feature
    const int base = blockIdx.x * BC;   // first batch row of this CTA

    // per-step keys: key_t = threefry((0,42), (0,t))  [partitionable split]
    Ks[g] = tf2x32(0u, 42u, 0u, (uint32_t)g);

    #pragma unroll
    for (int i = 0; i < BC; ++i) {
        int b = base + i; if (b >= BTOT) b = BTOT - 1;   // clamp (dupes never stored)
        Xs[i][g] = img[b * TS + g];                       // coalesced (g == t index here)
    }
    #pragma unroll
    for (int p = 0; p < NP; ++p) { Lp[p][g][0] = 0.f; Lp[p][g][1] = 0.f; }

    const float wih  = W_ih[g];
    const float bsum = b_ih[g] + b_hh[g];
    __syncthreads();

    for (int t = 0; t < TS; ++t) {
        const float a = (float)(257 - t) / 257.0f;        // a_t = (T - t + 1)/(T+1)
        const float sigma = sqrtf(a * (1.0f - a));
        const uint2 key = Ks[t];

        // acc[p] holds {arg(2p), arg(2p+1)} packed; init = x*w_ih + (b_ih + b_hh)
        unsigned long long acc[NP];
        #pragma unroll
        for (int p = 0; p < NP; ++p) {
            float alo = fmaf(Xs[2*p][t],   wih, bsum);
            float ahi = fmaf(Xs[2*p+1][t], wih, bsum);
            PACK2(acc[p], __float_as_uint(alo), __float_as_uint(ahi));
        }

        // matvec: acc[p] += sum_h W[g][h] * latent[{2p,2p+1}][h]  via packed fma.rn.f32x2
        float4 w4 = g_Wp[g];
        #pragma unroll 2
        for (int h4 = 0; h4 < 64; ++h4) {
            float4 wn = g_Wp[(((h4 + 1) & 63) << 8) + g];   // prefetch next
            unsigned long long wx, wy, wz, ww;
            PACK2(wx, __float_as_uint(w4.x), __float_as_uint(w4.x));
            PACK2(wy, __float_as_uint(w4.y), __float_as_uint(w4.y));
            PACK2(wz, __float_as_uint(w4.z), __float_as_uint(w4.z));
            PACK2(ww, __float_as_uint(w4.w), __float_as_uint(w4.w));
            #pragma unroll
            for (int p = 0; p < NP; ++p) {
                const ulonglong2* lp = (const ulonglong2*)&Lp[p][h4 * 4][0]; // broadcast LDS
                ulonglong2 l01 = lp[0];   // pairs for h=4h4, 4h4+1
                ulonglong2 l23 = lp[1];   // pairs for h=4h4+2, 4h4+3
                FMA2(acc[p], wx, l01.x);
                FMA2(acc[p], wy, l01.y);
                FMA2(acc[p], wz, l23.x);
                FMA2(acc[p], ww, l23.y);
            }
            w4 = wn;
        }

        // tanh + noise (does not touch Lp)
        float hv[BC], nz[BC];
        #pragma unroll
        for (int p = 0; p < NP; ++p) {
            uint32_t alo, ahi;
            UNPACK2(alo, ahi, acc[p]);
            hv[2*p]   = tanhf(__uint_as_float(alo));
            hv[2*p+1] = tanhf(__uint_as_float(ahi));
            nz[2*p]   = jax_normal(key, (uint32_t)((base + 2*p)     * HDIM + g));
            nz[2*p+1] = jax_normal(key, (uint32_t)((base + 2*p + 1) * HDIM + g));
        }

        __syncthreads();   // all matvec reads of Lp complete before updates
        #pragma unroll
        for (int p = 0; p < NP; ++p) {
            // latent = ((latent + x) + h) + sigma * (0.1 * normal)  — reference op order
            float l0 = Lp[p][g][0], l1 = Lp[p][g][1];
            l0 = l0 + Xs[2*p][t];   l0 = l0 + hv[2*p];   l0 = l0 + sigma * (0.1f * nz[2*p]);
            l1 = l1 + Xs[2*p+1][t]; l1 = l1 + hv[2*p+1]; l1 = l1 + sigma * (0.1f * nz[2*p+1]);
            Lp[p][g][0] = l0; Lp[p][g][1] = l1;
        }
        __syncthreads();   // updates visible before next step's matvec
    }

    #pragma unroll
    for (int p = 0; p < NP; ++p) {
        int b0 = base + 2*p, b1 = b0 + 1;
        if (b0 < BTOT) out[b0 * HDIM + g] = Lp[p][g][0];
        if (b1 < BTOT) out[b1 * HDIM + g] = Lp[p][g][1];
    }
}

extern "C" void kernel_launch(void* const* d_in, const int* in_sizes, int n_in,
                              void* d_out, int out_size) {
    // metadata order: T (int scalar), flat_img, W_ih, W_hh, b_ih, b_hh.
    // Be robust to T being absent: last 5 inputs are the arrays.
    int o = (n_in >= 6) ? (n_in - 5) : 0;
    const float* img  = (const float*)d_in[o + 0];
    const float* W_ih = (const float*)d_in[o + 1];
    const float* W_hh = (const float*)d_in[o + 2];
    const float* b_ih = (const float*)d_in[o + 3];
    const float* b_hh = (const float*)d_in[o + 4];

    pack_w_kernel<<<64, 256>>>(W_hh);
    drnet_kernel<<<NBLK, 256>>>(img, W_ih, b_ih, b_hh, (float*)d_out);
}